// round 2
// baseline (speedup 1.0000x reference)
#include <cuda_runtime.h>
#include <math.h>
#include <float.h>

#define BSZ 8192
#define FDIM 2048
#define DDIM 1024
#define HDIM 3072

// ---------------- scratch (__device__ globals; no allocations allowed) -------
__device__ float g_proj[(size_t)3 * BSZ * DDIM];   // 96 MB: proj, filled in-place
__device__ float g_Qn[(size_t)BSZ * DDIM];         // 32 MB: normalized query rows
__device__ float g_Cn[(size_t)BSZ * DDIM];         // 32 MB: normalized candidate rows
__device__ float g_S[16777216ull];                 // 64 MB: sim matrix (nq*nc <= B*B/4)
__device__ float g_h[(size_t)BSZ * DDIM];          // 32 MB: hidden layer
__device__ float g_nrm[BSZ];                       // per-bank-index norms (per modality, reused)
__device__ int   g_glist[3][BSZ];                  // g(i) = batch idx of i-th available row
__device__ int   g_qidx[3][BSZ];                   // query bank/batch index b (missing && b<Nb)
__device__ int   g_qrow[3][BSZ];                   // = glist[qidx]  (actual proj row of query vec)
__device__ int   g_cidx[3][BSZ];                   // candidate bank index j (avail[j] && j<Nb)
__device__ int   g_crow[3][BSZ];                   // = glist[cidx]  (actual proj row of candidate)
__device__ int   g_cnt[3][4];                      // [Nb, nq, nc, -]

// ---------------- setup: masks, scans, compacted index lists -----------------
__global__ void __launch_bounds__(1024) setup_kernel(const int* __restrict__ missing) {
    __shared__ int sh[1024];
    const int t = threadIdx.x;
    const int base = t * 8;
    for (int m = 0; m < 3; m++) {
        const int tag = m + 1;
        int a[8];
        // ---- pass 1: availability scan -> glist, Nb
        int cnt = 0;
        #pragma unroll
        for (int j = 0; j < 8; j++) { a[j] = (missing[base + j] != tag) ? 1 : 0; cnt += a[j]; }
        sh[t] = cnt; __syncthreads();
        for (int off = 1; off < 1024; off <<= 1) {
            int v = (t >= off) ? sh[t - off] : 0; __syncthreads();
            sh[t] += v; __syncthreads();
        }
        const int Nb = sh[1023];
        int pos = sh[t] - cnt;
        #pragma unroll
        for (int j = 0; j < 8; j++) if (a[j]) g_glist[m][pos++] = base + j;
        if (t == 0) g_cnt[m][0] = Nb;
        __syncthreads();
        // ---- pass 2: queries (missing && b < Nb) -> qidx, qrow
        int qf[8]; cnt = 0;
        #pragma unroll
        for (int j = 0; j < 8; j++) {
            qf[j] = ((missing[base + j] == tag) && (base + j < Nb)) ? 1 : 0; cnt += qf[j];
        }
        sh[t] = cnt; __syncthreads();
        for (int off = 1; off < 1024; off <<= 1) {
            int v = (t >= off) ? sh[t - off] : 0; __syncthreads();
            sh[t] += v; __syncthreads();
        }
        const int nq = sh[1023];
        pos = sh[t] - cnt;
        #pragma unroll
        for (int j = 0; j < 8; j++) if (qf[j]) {
            g_qidx[m][pos] = base + j;
            g_qrow[m][pos] = g_glist[m][base + j];
            pos++;
        }
        if (t == 0) g_cnt[m][1] = nq;
        __syncthreads();
        // ---- pass 3: candidate columns (avail[j] && j < Nb) -> cidx, crow
        int cf[8]; cnt = 0;
        #pragma unroll
        for (int j = 0; j < 8; j++) { cf[j] = (a[j] && (base + j < Nb)) ? 1 : 0; cnt += cf[j]; }
        sh[t] = cnt; __syncthreads();
        for (int off = 1; off < 1024; off <<= 1) {
            int v = (t >= off) ? sh[t - off] : 0; __syncthreads();
            sh[t] += v; __syncthreads();
        }
        const int nc = sh[1023];
        pos = sh[t] - cnt;
        #pragma unroll
        for (int j = 0; j < 8; j++) if (cf[j]) {
            g_cidx[m][pos] = base + j;
            g_crow[m][pos] = g_glist[m][base + j];
            pos++;
        }
        if (t == 0) g_cnt[m][2] = nc;
        __syncthreads();
    }
}

// ---------------- proj GEMM: C = X(8192x2048) @ W(2048x1024) + b -------------
__global__ void __launch_bounds__(256) gemm_proj(
    const float* __restrict__ A, const float* __restrict__ Bm,
    const float* __restrict__ bias, int modality)
{
    const int m0 = blockIdx.y * 128, n0 = blockIdx.x * 128;
    __shared__ float As[16][132];
    __shared__ float Bs[16][132];
    const int tid = threadIdx.x;
    const int ty = tid >> 4, tx = tid & 15;
    float acc[8][8] = {};
    float* __restrict__ C = g_proj + (size_t)modality * BSZ * DDIM;

    for (int k0 = 0; k0 < FDIM; k0 += 16) {
        #pragma unroll
        for (int l = tid; l < 512; l += 256) {
            int mm = l >> 2, kq = (l & 3) << 2;
            float4 v = *reinterpret_cast<const float4*>(A + (size_t)(m0 + mm) * FDIM + k0 + kq);
            As[kq + 0][mm] = v.x; As[kq + 1][mm] = v.y; As[kq + 2][mm] = v.z; As[kq + 3][mm] = v.w;
        }
        #pragma unroll
        for (int l = tid; l < 512; l += 256) {
            int kk = l >> 5, nq = (l & 31) << 2;
            *reinterpret_cast<float4*>(&Bs[kk][nq]) =
                *reinterpret_cast<const float4*>(Bm + (size_t)(k0 + kk) * DDIM + n0 + nq);
        }
        __syncthreads();
        #pragma unroll
        for (int kk = 0; kk < 16; kk++) {
            float af[8], bf[8];
            #pragma unroll
            for (int i = 0; i < 8; i++) af[i] = As[kk][ty * 8 + i];
            #pragma unroll
            for (int j = 0; j < 8; j++) bf[j] = Bs[kk][tx * 8 + j];
            #pragma unroll
            for (int i = 0; i < 8; i++)
                #pragma unroll
                for (int j = 0; j < 8; j++) acc[i][j] += af[i] * bf[j];
        }
        __syncthreads();
    }
    #pragma unroll
    for (int i = 0; i < 8; i++) {
        int r = m0 + ty * 8 + i;
        #pragma unroll
        for (int j = 0; j < 8; j++) {
            int c = n0 + tx * 8 + j;
            C[(size_t)r * DDIM + c] = acc[i][j] + bias[c];
        }
    }
}

// ---------------- per-bank-row L2 norms (rows i < Nb) -------------------------
__global__ void __launch_bounds__(256) knorm(int m) {
    const int i = blockIdx.x;
    if (i >= g_cnt[m][0]) return;
    const int row = g_glist[m][i];
    const float4* p = reinterpret_cast<const float4*>(
        g_proj + (size_t)m * BSZ * DDIM + (size_t)row * DDIM);
    float4 v = p[threadIdx.x];
    float s = v.x * v.x + v.y * v.y + v.z * v.z + v.w * v.w;
    #pragma unroll
    for (int off = 16; off > 0; off >>= 1) s += __shfl_down_sync(0xffffffffu, s, off);
    __shared__ float red[8];
    if ((threadIdx.x & 31) == 0) red[threadIdx.x >> 5] = s;
    __syncthreads();
    if (threadIdx.x == 0) {
        float tot = 0.f;
        #pragma unroll
        for (int w = 0; w < 8; w++) tot += red[w];
        g_nrm[i] = fmaxf(__fsqrt_rn(tot), 1e-8f);
    }
}

// ---------------- gather normalized query / candidate matrices ----------------
__global__ void __launch_bounds__(256) kgather(int m) {
    const int i = blockIdx.x, t = threadIdx.x;
    const float* __restrict__ projm = g_proj + (size_t)m * BSZ * DDIM;
    if (i < g_cnt[m][1]) {
        const float nr = g_nrm[g_qidx[m][i]];
        float4 v = reinterpret_cast<const float4*>(projm + (size_t)g_qrow[m][i] * DDIM)[t];
        float4 o = make_float4(__fdiv_rn(v.x, nr), __fdiv_rn(v.y, nr),
                               __fdiv_rn(v.z, nr), __fdiv_rn(v.w, nr));
        reinterpret_cast<float4*>(g_Qn + (size_t)i * DDIM)[t] = o;
    }
    if (i < g_cnt[m][2]) {
        const float nr = g_nrm[g_cidx[m][i]];
        float4 v = reinterpret_cast<const float4*>(projm + (size_t)g_crow[m][i] * DDIM)[t];
        float4 o = make_float4(__fdiv_rn(v.x, nr), __fdiv_rn(v.y, nr),
                               __fdiv_rn(v.z, nr), __fdiv_rn(v.w, nr));
        reinterpret_cast<float4*>(g_Cn + (size_t)i * DDIM)[t] = o;
    }
}

// ---------------- zero rows: missing && b >= Nb --------------------------------
__global__ void __launch_bounds__(256) kzero(const int* __restrict__ missing, int m) {
    const int b = blockIdx.x;
    if (missing[b] != m + 1) return;
    if (b < g_cnt[m][0]) return;
    reinterpret_cast<float4*>(g_proj + (size_t)m * BSZ * DDIM + (size_t)b * DDIM)[threadIdx.x] =
        make_float4(0.f, 0.f, 0.f, 0.f);
}

// ---------------- sim GEMM (NT): S[nq,nc] = Qn @ Cn^T, K=1024 ------------------
__global__ void __launch_bounds__(256) gemm_sim(int m) {
    const int M = g_cnt[m][1], N = g_cnt[m][2];
    const int m0 = blockIdx.y * 128, n0 = blockIdx.x * 128;
    if (m0 >= M || n0 >= N) return;
    __shared__ float As[16][132];
    __shared__ float Bs[16][132];
    const int tid = threadIdx.x;
    const int ty = tid >> 4, tx = tid & 15;
    float acc[8][8] = {};
    const float4 z4 = make_float4(0.f, 0.f, 0.f, 0.f);

    for (int k0 = 0; k0 < DDIM; k0 += 16) {
        #pragma unroll
        for (int l = tid; l < 512; l += 256) {
            int mm = l >> 2, kq = (l & 3) << 2;
            float4 v = (m0 + mm < M)
                ? *reinterpret_cast<const float4*>(g_Qn + (size_t)(m0 + mm) * DDIM + k0 + kq) : z4;
            As[kq + 0][mm] = v.x; As[kq + 1][mm] = v.y; As[kq + 2][mm] = v.z; As[kq + 3][mm] = v.w;
        }
        #pragma unroll
        for (int l = tid; l < 512; l += 256) {
            int nn = l >> 2, kq = (l & 3) << 2;
            float4 v = (n0 + nn < N)
                ? *reinterpret_cast<const float4*>(g_Cn + (size_t)(n0 + nn) * DDIM + k0 + kq) : z4;
            Bs[kq + 0][nn] = v.x; Bs[kq + 1][nn] = v.y; Bs[kq + 2][nn] = v.z; Bs[kq + 3][nn] = v.w;
        }
        __syncthreads();
        #pragma unroll
        for (int kk = 0; kk < 16; kk++) {
            float af[8], bf[8];
            #pragma unroll
            for (int i = 0; i < 8; i++) af[i] = As[kk][ty * 8 + i];
            #pragma unroll
            for (int j = 0; j < 8; j++) bf[j] = Bs[kk][tx * 8 + j];
            #pragma unroll
            for (int i = 0; i < 8; i++)
                #pragma unroll
                for (int j = 0; j < 8; j++) acc[i][j] += af[i] * bf[j];
        }
        __syncthreads();
    }
    #pragma unroll
    for (int i = 0; i < 8; i++) {
        int r = m0 + ty * 8 + i;
        if (r >= M) continue;
        #pragma unroll
        for (int j = 0; j < 8; j++) {
            int c = n0 + tx * 8 + j;
            if (c < N) g_S[(size_t)r * N + c] = acc[i][j];
        }
    }
}

// ---------------- top-3 + softmax + weighted gather, in-place fill -------------
__global__ void __launch_bounds__(256) ktopk(int m) {
    const int q = blockIdx.x;
    const int nq = g_cnt[m][1];
    if (q >= nq) return;
    const int nc = g_cnt[m][2];
    const int t = threadIdx.x;
    float* __restrict__ projm = g_proj + (size_t)m * BSZ * DDIM;
    float* __restrict__ dst = projm + (size_t)g_qidx[m][q] * DDIM;
    if (nc == 0) {  // any_valid == False -> zeros
        reinterpret_cast<float4*>(dst)[t] = make_float4(0.f, 0.f, 0.f, 0.f);
        return;
    }
    const float NEGINF = -INFINITY;
    const float* __restrict__ Srow = g_S + (size_t)q * nc;
    float v0 = NEGINF, v1 = NEGINF, v2 = NEGINF;
    int   i0 = 0x7fffffff, i1 = 0x7fffffff, i2 = 0x7fffffff;
    for (int c = t; c < nc; c += 256) {          // ascending c per thread -> ties keep smaller c
        float v = Srow[c];
        if (v > v2) {
            if (v > v1) {
                if (v > v0) { v2 = v1; i2 = i1; v1 = v0; i1 = i0; v0 = v; i0 = c; }
                else        { v2 = v1; i2 = i1; v1 = v;  i1 = c; }
            } else          { v2 = v;  i2 = c; }
        }
    }
    __shared__ float sv[768];
    __shared__ int   si[768];
    sv[t] = v0; sv[256 + t] = v1; sv[512 + t] = v2;
    si[t] = i0; si[256 + t] = i1; si[512 + t] = i2;
    __syncthreads();
    __shared__ float fw[3];
    __shared__ int   fr[3];
    if (t == 0) {
        float b0 = NEGINF, b1 = NEGINF, b2 = NEGINF;
        int   j0 = 0x7fffffff, j1 = 0x7fffffff, j2 = 0x7fffffff;
        for (int e = 0; e < 768; e++) {
            float v = sv[e]; int c = si[e];
            if ((v > b2) || (v == b2 && c < j2)) {
                if ((v > b1) || (v == b1 && c < j1)) {
                    if ((v > b0) || (v == b0 && c < j0)) {
                        b2 = b1; j2 = j1; b1 = b0; j1 = j0; b0 = v; j0 = c;
                    } else { b2 = b1; j2 = j1; b1 = v; j1 = c; }
                } else     { b2 = v; j2 = c; }
            }
        }
        // softmax over (b0,b1,b2); -inf -> weight 0 (matches jax softmax on -inf)
        float w0 = 1.0f;  // expf(b0-b0)
        float w1 = (b1 == NEGINF) ? 0.f : expf(b1 - b0);
        float w2 = (b2 == NEGINF) ? 0.f : expf(b2 - b0);
        float ws = w0 + w1 + w2;
        fw[0] = __fdiv_rn(w0, ws); fw[1] = __fdiv_rn(w1, ws); fw[2] = __fdiv_rn(w2, ws);
        fr[0] = (j0 == 0x7fffffff) ? 0 : g_crow[m][j0];
        fr[1] = (j1 == 0x7fffffff) ? 0 : g_crow[m][j1];
        fr[2] = (j2 == 0x7fffffff) ? 0 : g_crow[m][j2];
    }
    __syncthreads();
    const float w0 = fw[0], w1 = fw[1], w2 = fw[2];
    float4 a = reinterpret_cast<const float4*>(projm + (size_t)fr[0] * DDIM)[t];
    float4 b = reinterpret_cast<const float4*>(projm + (size_t)fr[1] * DDIM)[t];
    float4 c = reinterpret_cast<const float4*>(projm + (size_t)fr[2] * DDIM)[t];
    float4 o;
    o.x = w0 * a.x + w1 * b.x + w2 * c.x;
    o.y = w0 * a.y + w1 * b.y + w2 * c.y;
    o.z = w0 * a.z + w1 * b.z + w2 * c.z;
    o.w = w0 * a.w + w1 * b.w + w2 * c.w;
    reinterpret_cast<float4*>(dst)[t] = o;
}

// ---------------- MLP layer 1: h = relu(concat(proj) @ W1 + b1) ----------------
__global__ void __launch_bounds__(256) gemm_mlp1(
    const float* __restrict__ W1, const float* __restrict__ b1)
{
    const int m0 = blockIdx.y * 128, n0 = blockIdx.x * 128;
    __shared__ float As[16][132];
    __shared__ float Bs[16][132];
    const int tid = threadIdx.x;
    const int ty = tid >> 4, tx = tid & 15;
    float acc[8][8] = {};

    for (int k0 = 0; k0 < HDIM; k0 += 16) {
        const float* __restrict__ Abase = g_proj + (size_t)(k0 >> 10) * BSZ * DDIM;
        const int kin = k0 & 1023;
        #pragma unroll
        for (int l = tid; l < 512; l += 256) {
            int mm = l >> 2, kq = (l & 3) << 2;
            float4 v = *reinterpret_cast<const float4*>(Abase + (size_t)(m0 + mm) * DDIM + kin + kq);
            As[kq + 0][mm] = v.x; As[kq + 1][mm] = v.y; As[kq + 2][mm] = v.z; As[kq + 3][mm] = v.w;
        }
        #pragma unroll
        for (int l = tid; l < 512; l += 256) {
            int kk = l >> 5, nq = (l & 31) << 2;
            *reinterpret_cast<float4*>(&Bs[kk][nq]) =
                *reinterpret_cast<const float4*>(W1 + (size_t)(k0 + kk) * DDIM + n0 + nq);
        }
        __syncthreads();
        #pragma unroll
        for (int kk = 0; kk < 16; kk++) {
            float af[8], bf[8];
            #pragma unroll
            for (int i = 0; i < 8; i++) af[i] = As[kk][ty * 8 + i];
            #pragma unroll
            for (int j = 0; j < 8; j++) bf[j] = Bs[kk][tx * 8 + j];
            #pragma unroll
            for (int i = 0; i < 8; i++)
                #pragma unroll
                for (int j = 0; j < 8; j++) acc[i][j] += af[i] * bf[j];
        }
        __syncthreads();
    }
    #pragma unroll
    for (int i = 0; i < 8; i++) {
        int r = m0 + ty * 8 + i;
        #pragma unroll
        for (int j = 0; j < 8; j++) {
            int cc = n0 + tx * 8 + j;
            g_h[(size_t)r * DDIM + cc] = fmaxf(acc[i][j] + b1[cc], 0.f);
        }
    }
}

// ---------------- MLP layer 2: out = h @ W2 + b2 -------------------------------
__global__ void __launch_bounds__(256) kmlp2(
    const float* __restrict__ W2, const float* __restrict__ b2, float* __restrict__ out)
{
    const int b = blockIdx.x, t = threadIdx.x;
    float4 h = reinterpret_cast<const float4*>(g_h + (size_t)b * DDIM)[t];
    float4 w = reinterpret_cast<const float4*>(W2)[t];
    float s = h.x * w.x + h.y * w.y + h.z * w.z + h.w * w.w;
    #pragma unroll
    for (int off = 16; off > 0; off >>= 1) s += __shfl_down_sync(0xffffffffu, s, off);
    __shared__ float red[8];
    if ((t & 31) == 0) red[t >> 5] = s;
    __syncthreads();
    if (t == 0) {
        float tot = 0.f;
        #pragma unroll
        for (int wq = 0; wq < 8; wq++) tot += red[wq];
        out[b] = tot + b2[0];
    }
}

// ---------------- launch ------------------------------------------------------
extern "C" void kernel_launch(void* const* d_in, const int* in_sizes, int n_in,
                              void* d_out, int out_size) {
    const float* x[3]  = { (const float*)d_in[0], (const float*)d_in[1], (const float*)d_in[2] };
    const int* missing = (const int*)d_in[3];
    const float* W[3]  = { (const float*)d_in[4], (const float*)d_in[6], (const float*)d_in[8] };
    const float* bb[3] = { (const float*)d_in[5], (const float*)d_in[7], (const float*)d_in[9] };
    const float* W1 = (const float*)d_in[10];
    const float* b1 = (const float*)d_in[11];
    const float* W2 = (const float*)d_in[12];
    const float* b2 = (const float*)d_in[13];
    float* out = (float*)d_out;

    setup_kernel<<<1, 1024>>>(missing);

    dim3 gp(DDIM / 128, BSZ / 128);                 // (8, 64)
    for (int m = 0; m < 3; m++)
        gemm_proj<<<gp, 256>>>(x[m], W[m], bb[m], m);

    dim3 gs(64, 64);                                // worst-case; blocks early-exit on runtime dims
    for (int m = 0; m < 3; m++) {
        knorm<<<BSZ, 256>>>(m);
        kgather<<<BSZ, 256>>>(m);
        kzero<<<BSZ, 256>>>(missing, m);
        gemm_sim<<<gs, 256>>>(m);
        ktopk<<<BSZ, 256>>>(m);
    }

    gemm_mlp1<<<gp, 256>>>(W1, b1);
    kmlp2<<<BSZ, 256>>>(W2, b2, out);
}

// round 3
// speedup vs baseline: 1.0006x; 1.0006x over previous
#include <cuda_runtime.h>
#include <math.h>
#include <float.h>

#define BSZ 8192
#define FDIM 2048
#define DDIM 1024
#define HDIM 3072

// ---------------- scratch (__device__ globals; no allocations allowed) -------
__device__ float g_proj[(size_t)3 * BSZ * DDIM];   // 96 MB: proj, filled in-place
__device__ float g_Qn[(size_t)BSZ * DDIM];         // 32 MB: normalized query rows
__device__ float g_Cn[(size_t)BSZ * DDIM];         // 32 MB: normalized candidate rows
__device__ float g_S[16777216ull];                 // 64 MB: sim matrix (nq*nc <= B*B/4)
__device__ float g_h[(size_t)BSZ * DDIM];          // 32 MB: hidden layer
__device__ float g_nrm[BSZ];                       // per-bank-index norms (per modality, reused)
__device__ int   g_glist[3][BSZ];                  // g(i) = batch idx of i-th available row
__device__ int   g_qidx[3][BSZ];                   // query bank/batch index b (missing && b<Nb)
__device__ int   g_qrow[3][BSZ];                   // = glist[qidx]  (actual proj row of query vec)
__device__ int   g_cidx[3][BSZ];                   // candidate bank index j (avail[j] && j<Nb)
__device__ int   g_crow[3][BSZ];                   // = glist[cidx]  (actual proj row of candidate)
__device__ int   g_cnt[3][4];                      // [Nb, nq, nc, -]

// ---------------- setup: masks, scans, compacted index lists -----------------
__global__ void __launch_bounds__(1024) setup_kernel(const int* __restrict__ missing) {
    __shared__ int sh[1024];
    const int t = threadIdx.x;
    const int base = t * 8;
    for (int m = 0; m < 3; m++) {
        const int tag = m + 1;
        int a[8];
        // ---- pass 1: availability scan -> glist, Nb
        int cnt = 0;
        #pragma unroll
        for (int j = 0; j < 8; j++) { a[j] = (missing[base + j] != tag) ? 1 : 0; cnt += a[j]; }
        sh[t] = cnt; __syncthreads();
        for (int off = 1; off < 1024; off <<= 1) {
            int v = (t >= off) ? sh[t - off] : 0; __syncthreads();
            sh[t] += v; __syncthreads();
        }
        const int Nb = sh[1023];
        int pos = sh[t] - cnt;
        #pragma unroll
        for (int j = 0; j < 8; j++) if (a[j]) g_glist[m][pos++] = base + j;
        if (t == 0) g_cnt[m][0] = Nb;
        __syncthreads();
        // ---- pass 2: queries (missing && b < Nb) -> qidx, qrow
        int qf[8]; cnt = 0;
        #pragma unroll
        for (int j = 0; j < 8; j++) {
            qf[j] = ((missing[base + j] == tag) && (base + j < Nb)) ? 1 : 0; cnt += qf[j];
        }
        sh[t] = cnt; __syncthreads();
        for (int off = 1; off < 1024; off <<= 1) {
            int v = (t >= off) ? sh[t - off] : 0; __syncthreads();
            sh[t] += v; __syncthreads();
        }
        const int nq = sh[1023];
        pos = sh[t] - cnt;
        #pragma unroll
        for (int j = 0; j < 8; j++) if (qf[j]) {
            g_qidx[m][pos] = base + j;
            g_qrow[m][pos] = g_glist[m][base + j];
            pos++;
        }
        if (t == 0) g_cnt[m][1] = nq;
        __syncthreads();
        // ---- pass 3: candidate columns (avail[j] && j < Nb) -> cidx, crow
        int cf[8]; cnt = 0;
        #pragma unroll
        for (int j = 0; j < 8; j++) { cf[j] = (a[j] && (base + j < Nb)) ? 1 : 0; cnt += cf[j]; }
        sh[t] = cnt; __syncthreads();
        for (int off = 1; off < 1024; off <<= 1) {
            int v = (t >= off) ? sh[t - off] : 0; __syncthreads();
            sh[t] += v; __syncthreads();
        }
        const int nc = sh[1023];
        pos = sh[t] - cnt;
        #pragma unroll
        for (int j = 0; j < 8; j++) if (cf[j]) {
            g_cidx[m][pos] = base + j;
            g_crow[m][pos] = g_glist[m][base + j];
            pos++;
        }
        if (t == 0) g_cnt[m][2] = nc;
        __syncthreads();
    }
}

// ---------------- proj GEMM: C = X(8192x2048) @ W(2048x1024) + b -------------
__global__ void __launch_bounds__(256) gemm_proj(
    const float* __restrict__ A, const float* __restrict__ Bm,
    const float* __restrict__ bias, int modality)
{
    const int m0 = blockIdx.y * 128, n0 = blockIdx.x * 128;
    __shared__ float As[16][132];
    __shared__ float Bs[16][132];
    const int tid = threadIdx.x;
    const int ty = tid >> 4, tx = tid & 15;
    float acc[8][8] = {};
    float* __restrict__ C = g_proj + (size_t)modality * BSZ * DDIM;

    for (int k0 = 0; k0 < FDIM; k0 += 16) {
        #pragma unroll
        for (int l = tid; l < 512; l += 256) {
            int mm = l >> 2, kq = (l & 3) << 2;
            float4 v = *reinterpret_cast<const float4*>(A + (size_t)(m0 + mm) * FDIM + k0 + kq);
            As[kq + 0][mm] = v.x; As[kq + 1][mm] = v.y; As[kq + 2][mm] = v.z; As[kq + 3][mm] = v.w;
        }
        #pragma unroll
        for (int l = tid; l < 512; l += 256) {
            int kk = l >> 5, nq = (l & 31) << 2;
            *reinterpret_cast<float4*>(&Bs[kk][nq]) =
                *reinterpret_cast<const float4*>(Bm + (size_t)(k0 + kk) * DDIM + n0 + nq);
        }
        __syncthreads();
        #pragma unroll
        for (int kk = 0; kk < 16; kk++) {
            float af[8], bf[8];
            #pragma unroll
            for (int i = 0; i < 8; i++) af[i] = As[kk][ty * 8 + i];
            #pragma unroll
            for (int j = 0; j < 8; j++) bf[j] = Bs[kk][tx * 8 + j];
            #pragma unroll
            for (int i = 0; i < 8; i++)
                #pragma unroll
                for (int j = 0; j < 8; j++) acc[i][j] += af[i] * bf[j];
        }
        __syncthreads();
    }
    #pragma unroll
    for (int i = 0; i < 8; i++) {
        int r = m0 + ty * 8 + i;
        #pragma unroll
        for (int j = 0; j < 8; j++) {
            int c = n0 + tx * 8 + j;
            C[(size_t)r * DDIM + c] = acc[i][j] + bias[c];
        }
    }
}

// ---------------- per-bank-row L2 norms (rows i < Nb) -------------------------
__global__ void __launch_bounds__(256) knorm(int m) {
    const int i = blockIdx.x;
    if (i >= g_cnt[m][0]) return;
    const int row = g_glist[m][i];
    const float4* p = reinterpret_cast<const float4*>(
        g_proj + (size_t)m * BSZ * DDIM + (size_t)row * DDIM);
    float4 v = p[threadIdx.x];
    float s = v.x * v.x + v.y * v.y + v.z * v.z + v.w * v.w;
    #pragma unroll
    for (int off = 16; off > 0; off >>= 1) s += __shfl_down_sync(0xffffffffu, s, off);
    __shared__ float red[8];
    if ((threadIdx.x & 31) == 0) red[threadIdx.x >> 5] = s;
    __syncthreads();
    if (threadIdx.x == 0) {
        float tot = 0.f;
        #pragma unroll
        for (int w = 0; w < 8; w++) tot += red[w];
        g_nrm[i] = fmaxf(__fsqrt_rn(tot), 1e-8f);
    }
}

// ---------------- gather normalized query / candidate matrices ----------------
__global__ void __launch_bounds__(256) kgather(int m) {
    const int i = blockIdx.x, t = threadIdx.x;
    const float* __restrict__ projm = g_proj + (size_t)m * BSZ * DDIM;
    if (i < g_cnt[m][1]) {
        const float nr = g_nrm[g_qidx[m][i]];
        float4 v = reinterpret_cast<const float4*>(projm + (size_t)g_qrow[m][i] * DDIM)[t];
        float4 o = make_float4(__fdiv_rn(v.x, nr), __fdiv_rn(v.y, nr),
                               __fdiv_rn(v.z, nr), __fdiv_rn(v.w, nr));
        reinterpret_cast<float4*>(g_Qn + (size_t)i * DDIM)[t] = o;
    }
    if (i < g_cnt[m][2]) {
        const float nr = g_nrm[g_cidx[m][i]];
        float4 v = reinterpret_cast<const float4*>(projm + (size_t)g_crow[m][i] * DDIM)[t];
        float4 o = make_float4(__fdiv_rn(v.x, nr), __fdiv_rn(v.y, nr),
                               __fdiv_rn(v.z, nr), __fdiv_rn(v.w, nr));
        reinterpret_cast<float4*>(g_Cn + (size_t)i * DDIM)[t] = o;
    }
}

// ---------------- zero rows: missing && b >= Nb --------------------------------
__global__ void __launch_bounds__(256) kzero(const int* __restrict__ missing, int m) {
    const int b = blockIdx.x;
    if (missing[b] != m + 1) return;
    if (b < g_cnt[m][0]) return;
    reinterpret_cast<float4*>(g_proj + (size_t)m * BSZ * DDIM + (size_t)b * DDIM)[threadIdx.x] =
        make_float4(0.f, 0.f, 0.f, 0.f);
}

// ---------------- sim GEMM (NT): S[nq,nc] = Qn @ Cn^T, K=1024 ------------------
__global__ void __launch_bounds__(256) gemm_sim(int m) {
    const int M = g_cnt[m][1], N = g_cnt[m][2];
    const int m0 = blockIdx.y * 128, n0 = blockIdx.x * 128;
    if (m0 >= M || n0 >= N) return;
    __shared__ float As[16][132];
    __shared__ float Bs[16][132];
    const int tid = threadIdx.x;
    const int ty = tid >> 4, tx = tid & 15;
    float acc[8][8] = {};
    const float4 z4 = make_float4(0.f, 0.f, 0.f, 0.f);

    for (int k0 = 0; k0 < DDIM; k0 += 16) {
        #pragma unroll
        for (int l = tid; l < 512; l += 256) {
            int mm = l >> 2, kq = (l & 3) << 2;
            float4 v = (m0 + mm < M)
                ? *reinterpret_cast<const float4*>(g_Qn + (size_t)(m0 + mm) * DDIM + k0 + kq) : z4;
            As[kq + 0][mm] = v.x; As[kq + 1][mm] = v.y; As[kq + 2][mm] = v.z; As[kq + 3][mm] = v.w;
        }
        #pragma unroll
        for (int l = tid; l < 512; l += 256) {
            int nn = l >> 2, kq = (l & 3) << 2;
            float4 v = (n0 + nn < N)
                ? *reinterpret_cast<const float4*>(g_Cn + (size_t)(n0 + nn) * DDIM + k0 + kq) : z4;
            Bs[kq + 0][nn] = v.x; Bs[kq + 1][nn] = v.y; Bs[kq + 2][nn] = v.z; Bs[kq + 3][nn] = v.w;
        }
        __syncthreads();
        #pragma unroll
        for (int kk = 0; kk < 16; kk++) {
            float af[8], bf[8];
            #pragma unroll
            for (int i = 0; i < 8; i++) af[i] = As[kk][ty * 8 + i];
            #pragma unroll
            for (int j = 0; j < 8; j++) bf[j] = Bs[kk][tx * 8 + j];
            #pragma unroll
            for (int i = 0; i < 8; i++)
                #pragma unroll
                for (int j = 0; j < 8; j++) acc[i][j] += af[i] * bf[j];
        }
        __syncthreads();
    }
    #pragma unroll
    for (int i = 0; i < 8; i++) {
        int r = m0 + ty * 8 + i;
        if (r >= M) continue;
        #pragma unroll
        for (int j = 0; j < 8; j++) {
            int c = n0 + tx * 8 + j;
            if (c < N) g_S[(size_t)r * N + c] = acc[i][j];
        }
    }
}

// ---------------- top-3 + softmax + weighted gather, in-place fill -------------
__global__ void __launch_bounds__(256) ktopk(int m) {
    const int q = blockIdx.x;
    const int nq = g_cnt[m][1];
    if (q >= nq) return;
    const int nc = g_cnt[m][2];
    const int t = threadIdx.x;
    float* __restrict__ projm = g_proj + (size_t)m * BSZ * DDIM;
    float* __restrict__ dst = projm + (size_t)g_qidx[m][q] * DDIM;
    if (nc == 0) {  // any_valid == False -> zeros
        reinterpret_cast<float4*>(dst)[t] = make_float4(0.f, 0.f, 0.f, 0.f);
        return;
    }
    const float NEGINF = -INFINITY;
    const float* __restrict__ Srow = g_S + (size_t)q * nc;
    float v0 = NEGINF, v1 = NEGINF, v2 = NEGINF;
    int   i0 = 0x7fffffff, i1 = 0x7fffffff, i2 = 0x7fffffff;
    for (int c = t; c < nc; c += 256) {          // ascending c per thread -> ties keep smaller c
        float v = Srow[c];
        if (v > v2) {
            if (v > v1) {
                if (v > v0) { v2 = v1; i2 = i1; v1 = v0; i1 = i0; v0 = v; i0 = c; }
                else        { v2 = v1; i2 = i1; v1 = v;  i1 = c; }
            } else          { v2 = v;  i2 = c; }
        }
    }
    __shared__ float sv[768];
    __shared__ int   si[768];
    sv[t] = v0; sv[256 + t] = v1; sv[512 + t] = v2;
    si[t] = i0; si[256 + t] = i1; si[512 + t] = i2;
    __syncthreads();
    __shared__ float fw[3];
    __shared__ int   fr[3];
    if (t == 0) {
        float b0 = NEGINF, b1 = NEGINF, b2 = NEGINF;
        int   j0 = 0x7fffffff, j1 = 0x7fffffff, j2 = 0x7fffffff;
        for (int e = 0; e < 768; e++) {
            float v = sv[e]; int c = si[e];
            if ((v > b2) || (v == b2 && c < j2)) {
                if ((v > b1) || (v == b1 && c < j1)) {
                    if ((v > b0) || (v == b0 && c < j0)) {
                        b2 = b1; j2 = j1; b1 = b0; j1 = j0; b0 = v; j0 = c;
                    } else { b2 = b1; j2 = j1; b1 = v; j1 = c; }
                } else     { b2 = v; j2 = c; }
            }
        }
        // softmax over (b0,b1,b2); -inf -> weight 0 (matches jax softmax on -inf)
        float w0 = 1.0f;  // expf(b0-b0)
        float w1 = (b1 == NEGINF) ? 0.f : expf(b1 - b0);
        float w2 = (b2 == NEGINF) ? 0.f : expf(b2 - b0);
        float ws = w0 + w1 + w2;
        fw[0] = __fdiv_rn(w0, ws); fw[1] = __fdiv_rn(w1, ws); fw[2] = __fdiv_rn(w2, ws);
        fr[0] = (j0 == 0x7fffffff) ? 0 : g_crow[m][j0];
        fr[1] = (j1 == 0x7fffffff) ? 0 : g_crow[m][j1];
        fr[2] = (j2 == 0x7fffffff) ? 0 : g_crow[m][j2];
    }
    __syncthreads();
    const float w0 = fw[0], w1 = fw[1], w2 = fw[2];
    float4 a = reinterpret_cast<const float4*>(projm + (size_t)fr[0] * DDIM)[t];
    float4 b = reinterpret_cast<const float4*>(projm + (size_t)fr[1] * DDIM)[t];
    float4 c = reinterpret_cast<const float4*>(projm + (size_t)fr[2] * DDIM)[t];
    float4 o;
    o.x = w0 * a.x + w1 * b.x + w2 * c.x;
    o.y = w0 * a.y + w1 * b.y + w2 * c.y;
    o.z = w0 * a.z + w1 * b.z + w2 * c.z;
    o.w = w0 * a.w + w1 * b.w + w2 * c.w;
    reinterpret_cast<float4*>(dst)[t] = o;
}

// ---------------- MLP layer 1: h = relu(concat(proj) @ W1 + b1) ----------------
__global__ void __launch_bounds__(256) gemm_mlp1(
    const float* __restrict__ W1, const float* __restrict__ b1)
{
    const int m0 = blockIdx.y * 128, n0 = blockIdx.x * 128;
    __shared__ float As[16][132];
    __shared__ float Bs[16][132];
    const int tid = threadIdx.x;
    const int ty = tid >> 4, tx = tid & 15;
    float acc[8][8] = {};

    for (int k0 = 0; k0 < HDIM; k0 += 16) {
        const float* __restrict__ Abase = g_proj + (size_t)(k0 >> 10) * BSZ * DDIM;
        const int kin = k0 & 1023;
        #pragma unroll
        for (int l = tid; l < 512; l += 256) {
            int mm = l >> 2, kq = (l & 3) << 2;
            float4 v = *reinterpret_cast<const float4*>(Abase + (size_t)(m0 + mm) * DDIM + kin + kq);
            As[kq + 0][mm] = v.x; As[kq + 1][mm] = v.y; As[kq + 2][mm] = v.z; As[kq + 3][mm] = v.w;
        }
        #pragma unroll
        for (int l = tid; l < 512; l += 256) {
            int kk = l >> 5, nq = (l & 31) << 2;
            *reinterpret_cast<float4*>(&Bs[kk][nq]) =
                *reinterpret_cast<const float4*>(W1 + (size_t)(k0 + kk) * DDIM + n0 + nq);
        }
        __syncthreads();
        #pragma unroll
        for (int kk = 0; kk < 16; kk++) {
            float af[8], bf[8];
            #pragma unroll
            for (int i = 0; i < 8; i++) af[i] = As[kk][ty * 8 + i];
            #pragma unroll
            for (int j = 0; j < 8; j++) bf[j] = Bs[kk][tx * 8 + j];
            #pragma unroll
            for (int i = 0; i < 8; i++)
                #pragma unroll
                for (int j = 0; j < 8; j++) acc[i][j] += af[i] * bf[j];
        }
        __syncthreads();
    }
    #pragma unroll
    for (int i = 0; i < 8; i++) {
        int r = m0 + ty * 8 + i;
        #pragma unroll
        for (int j = 0; j < 8; j++) {
            int cc = n0 + tx * 8 + j;
            g_h[(size_t)r * DDIM + cc] = fmaxf(acc[i][j] + b1[cc], 0.f);
        }
    }
}

// ---------------- MLP layer 2: out = h @ W2 + b2 -------------------------------
__global__ void __launch_bounds__(256) kmlp2(
    const float* __restrict__ W2, const float* __restrict__ b2, float* __restrict__ out)
{
    const int b = blockIdx.x, t = threadIdx.x;
    float4 h = reinterpret_cast<const float4*>(g_h + (size_t)b * DDIM)[t];
    float4 w = reinterpret_cast<const float4*>(W2)[t];
    float s = h.x * w.x + h.y * w.y + h.z * w.z + h.w * w.w;
    #pragma unroll
    for (int off = 16; off > 0; off >>= 1) s += __shfl_down_sync(0xffffffffu, s, off);
    __shared__ float red[8];
    if ((t & 31) == 0) red[t >> 5] = s;
    __syncthreads();
    if (t == 0) {
        float tot = 0.f;
        #pragma unroll
        for (int wq = 0; wq < 8; wq++) tot += red[wq];
        out[b] = tot + b2[0];
    }
}

// ---------------- launch ------------------------------------------------------
extern "C" void kernel_launch(void* const* d_in, const int* in_sizes, int n_in,
                              void* d_out, int out_size) {
    const float* x[3]  = { (const float*)d_in[0], (const float*)d_in[1], (const float*)d_in[2] };
    const int* missing = (const int*)d_in[3];
    const float* W[3]  = { (const float*)d_in[4], (const float*)d_in[6], (const float*)d_in[8] };
    const float* bb[3] = { (const float*)d_in[5], (const float*)d_in[7], (const float*)d_in[9] };
    const float* W1 = (const float*)d_in[10];
    const float* b1 = (const float*)d_in[11];
    const float* W2 = (const float*)d_in[12];
    const float* b2 = (const float*)d_in[13];
    float* out = (float*)d_out;

    setup_kernel<<<1, 1024>>>(missing);

    dim3 gp(DDIM / 128, BSZ / 128);                 // (8, 64)
    for (int m = 0; m < 3; m++)
        gemm_proj<<<gp, 256>>>(x[m], W[m], bb[m], m);

    dim3 gs(64, 64);                                // worst-case; blocks early-exit on runtime dims
    for (int m = 0; m < 3; m++) {
        knorm<<<BSZ, 256>>>(m);
        kgather<<<BSZ, 256>>>(m);
        kzero<<<BSZ, 256>>>(missing, m);
        gemm_sim<<<gs, 256>>>(m);
        ktopk<<<BSZ, 256>>>(m);
    }

    gemm_mlp1<<<gp, 256>>>(W1, b1);
    kmlp2<<<BSZ, 256>>>(W2, b2, out);
}

// round 5
// speedup vs baseline: 1.1044x; 1.1037x over previous
#include <cuda_runtime.h>
#include <math.h>
#include <float.h>
#include <stdint.h>

#define BSZ 8192
#define FDIM 2048
#define DDIM 1024
#define HDIM 3072

// ---------------- scratch ------------------------------------------------------
__device__ float g_proj[(size_t)3 * BSZ * DDIM];
__device__ float g_Qn[(size_t)BSZ * DDIM];
__device__ float g_Cn[(size_t)BSZ * DDIM];
__device__ float g_S[16777216ull];
__device__ float g_h[(size_t)BSZ * DDIM];
__device__ float g_Wt[(size_t)3 * DDIM * FDIM];    // W^T per modality [1024][2048]
__device__ float g_W1t[(size_t)DDIM * HDIM];       // W1^T [1024][3072]
__device__ float g_nrm[BSZ];
__device__ int   g_glist[3][BSZ];
__device__ int   g_qidx[3][BSZ];
__device__ int   g_qrow[3][BSZ];
__device__ int   g_cidx[3][BSZ];
__device__ int   g_crow[3][BSZ];
__device__ int   g_cnt[3][4];

// ---------------- tf32 helpers (baseline PTX, no 'a'-suffix features) -----------
__device__ __forceinline__ uint32_t tf32hi(float x) {
    uint32_t u;
    asm("cvt.rna.tf32.f32 %0, %1;" : "=r"(u) : "f"(x));
    return u;
}
__device__ __forceinline__ uint32_t tf32lo(float x, uint32_t hi) {
    return tf32hi(x - __uint_as_float(hi));
}
__device__ __forceinline__ void mma8(float* d, const uint32_t* a, const uint32_t* b) {
    asm volatile(
        "mma.sync.aligned.m16n8k8.row.col.f32.tf32.tf32.f32 "
        "{%0,%1,%2,%3}, {%4,%5,%6,%7}, {%8,%9}, {%0,%1,%2,%3};"
        : "+f"(d[0]), "+f"(d[1]), "+f"(d[2]), "+f"(d[3])
        : "r"(a[0]), "r"(a[1]), "r"(a[2]), "r"(a[3]), "r"(b[0]), "r"(b[1]));
}

// ---------------- HMMA GEMM core -------------------------------------------------
// CTA tile 128x128, K-chunks of 16, double-buffered smem (2 x (8KB A + 8KB B)).
// smem layout is fragment-permuted for m16n8k8:
//   A: float idx = ((kstep*8 + mtile)*32 + (m&7)*4 + (k&3))*4 + (k&4?2:0)+(m&8?1:0)
//   B: float idx = ((kstep*16 + ntile)*32 + (n&7)*4 + (k&3))*2 + (k&4?1:0)
// so each lane loads its A fragment as one float4 and B fragment as one float2.
struct GA {
    const float* Ab;   // A base (non-proj mode)
    int ldA;
    int projA;         // A = concat(g_proj) addressed by k>>10
    const float* Bt;   // B^T, K-major [N][K]
    int ldB;
    int m0, n0, Mlim, Nlim;
};

__device__ __forceinline__ void g_load(const GA& g, int kc, float4 va[2], float4 vb[2]) {
    const int tid = threadIdx.x;
    const float4 z = make_float4(0.f, 0.f, 0.f, 0.f);
    const float* Abase = g.projA
        ? g_proj + (size_t)(kc >> 10) * BSZ * DDIM + (kc & 1023)
        : g.Ab + kc;
    #pragma unroll
    for (int u = 0; u < 2; u++) {
        const int idx = tid + u * 256;
        const int r = idx >> 2, kq = idx & 3;
        va[u] = (g.m0 + r < g.Mlim)
            ? *(const float4*)(Abase + (size_t)(g.m0 + r) * g.ldA + kq * 4) : z;
        vb[u] = (g.n0 + r < g.Nlim)
            ? *(const float4*)(g.Bt + (size_t)(g.n0 + r) * g.ldB + kc + kq * 4) : z;
    }
}

__device__ __forceinline__ void g_sts(float* As, float* Bs,
                                      const float4 va[2], const float4 vb[2]) {
    const int tid = threadIdx.x;
    #pragma unroll
    for (int u = 0; u < 2; u++) {
        const int idx = tid + u * 256;
        const int m = idx >> 2, kq = idx & 3;
        float* da = As + (((kq >> 1) * 8 + (m >> 4)) * 32 + (m & 7) * 4) * 4
                       + (kq & 1) * 2 + ((m >> 3) & 1);
        da[0] = va[u].x; da[4] = va[u].y; da[8] = va[u].z; da[12] = va[u].w;
        float* db = Bs + (((kq >> 1) * 16 + (m >> 3)) * 32 + (m & 7) * 4) * 2
                       + (kq & 1);
        db[0] = vb[u].x; db[2] = vb[u].y; db[4] = vb[u].z; db[6] = vb[u].w;
    }
}

__device__ __forceinline__ void g_compute(const float* As, const float* Bs,
                                          float acc[4][4][4]) {
    const int lane = threadIdx.x & 31, wid = threadIdx.x >> 5;
    const int wm = (wid & 1) * 64, wn = (wid >> 1) * 32;
    #pragma unroll
    for (int s = 0; s < 2; s++) {
        uint32_t Ah[4][4], Al[4][4], Bh[4][2], Bl[4][2];
        #pragma unroll
        for (int i = 0; i < 4; i++) {
            const float4 a = *(const float4*)(As + ((s * 8 + (wm >> 4) + i) * 32 + lane) * 4);
            Ah[i][0] = tf32hi(a.x); Al[i][0] = tf32lo(a.x, Ah[i][0]);
            Ah[i][1] = tf32hi(a.y); Al[i][1] = tf32lo(a.y, Ah[i][1]);
            Ah[i][2] = tf32hi(a.z); Al[i][2] = tf32lo(a.z, Ah[i][2]);
            Ah[i][3] = tf32hi(a.w); Al[i][3] = tf32lo(a.w, Ah[i][3]);
        }
        #pragma unroll
        for (int j = 0; j < 4; j++) {
            const float2 b = *(const float2*)(Bs + ((s * 16 + (wn >> 3) + j) * 32 + lane) * 2);
            Bh[j][0] = tf32hi(b.x); Bl[j][0] = tf32lo(b.x, Bh[j][0]);
            Bh[j][1] = tf32hi(b.y); Bl[j][1] = tf32lo(b.y, Bh[j][1]);
        }
        #pragma unroll
        for (int i = 0; i < 4; i++)
            #pragma unroll
            for (int j = 0; j < 4; j++) {
                mma8(acc[i][j], Ah[i], Bl[j]);   // low-order terms first
                mma8(acc[i][j], Al[i], Bh[j]);
                mma8(acc[i][j], Ah[i], Bh[j]);
            }
    }
}

__device__ __forceinline__ void hmma_gemm(const GA& g, int K,
                                          float (*As)[2048], float (*Bs)[2048],
                                          float acc[4][4][4]) {
    float4 va[2], vb[2];
    g_load(g, 0, va, vb);
    g_sts(As[0], Bs[0], va, vb);
    __syncthreads();
    const int nch = K / 16;
    for (int ic = 0; ic < nch; ic++) {
        const int buf = ic & 1;
        const bool more = (ic + 1) < nch;
        if (more) g_load(g, (ic + 1) * 16, va, vb);
        g_compute(As[buf], Bs[buf], acc);
        __syncthreads();
        if (more) g_sts(As[buf ^ 1], Bs[buf ^ 1], va, vb);
        __syncthreads();
    }
}

// ---------------- GEMM + bias(+relu): modes 0..2 = proj[m], 3 = mlp1 -------------
__global__ void __launch_bounds__(256) tgemm_bias(
    int mode, const float* __restrict__ A, const float* __restrict__ bias)
{
    __shared__ float As[2][2048];
    __shared__ float Bs[2][2048];
    const int m0 = blockIdx.y * 128, n0 = blockIdx.x * 128;
    GA g;
    float* out;
    int K, relu;
    if (mode < 3) {
        g = { A, FDIM, 0, g_Wt + (size_t)mode * DDIM * FDIM, FDIM,
              m0, n0, 1 << 30, 1 << 30 };
        out = g_proj + (size_t)mode * BSZ * DDIM; K = FDIM; relu = 0;
    } else {
        g = { nullptr, DDIM, 1, g_W1t, HDIM, m0, n0, 1 << 30, 1 << 30 };
        out = g_h; K = HDIM; relu = 1;
    }
    float acc[4][4][4] = {};
    hmma_gemm(g, K, As, Bs, acc);

    const int lane = threadIdx.x & 31, wid = threadIdx.x >> 5;
    const int wm = (wid & 1) * 64, wn = (wid >> 1) * 32;
    #pragma unroll
    for (int i = 0; i < 4; i++) {
        const int r0 = m0 + wm + i * 16 + (lane >> 2);
        #pragma unroll
        for (int j = 0; j < 4; j++) {
            const int c = n0 + wn + j * 8 + (lane & 3) * 2;
            const float2 bv = *(const float2*)(bias + c);
            float2 o0 = make_float2(acc[i][j][0] + bv.x, acc[i][j][1] + bv.y);
            float2 o1 = make_float2(acc[i][j][2] + bv.x, acc[i][j][3] + bv.y);
            if (relu) {
                o0.x = fmaxf(o0.x, 0.f); o0.y = fmaxf(o0.y, 0.f);
                o1.x = fmaxf(o1.x, 0.f); o1.y = fmaxf(o1.y, 0.f);
            }
            *(float2*)(out + (size_t)r0 * DDIM + c) = o0;
            *(float2*)(out + (size_t)(r0 + 8) * DDIM + c) = o1;
        }
    }
}

// ---------------- sim GEMM: S[nq,nc] = Qn @ Cn^T ----------------------------------
__global__ void __launch_bounds__(256) tgemm_sim(int m) {
    const int M = g_cnt[m][1], N = g_cnt[m][2];
    const int m0 = blockIdx.y * 128, n0 = blockIdx.x * 128;
    if (m0 >= M || n0 >= N) return;
    __shared__ float As[2][2048];
    __shared__ float Bs[2][2048];
    GA g = { g_Qn, DDIM, 0, g_Cn, DDIM, m0, n0, M, N };
    float acc[4][4][4] = {};
    hmma_gemm(g, DDIM, As, Bs, acc);

    const int lane = threadIdx.x & 31, wid = threadIdx.x >> 5;
    const int wm = (wid & 1) * 64, wn = (wid >> 1) * 32;
    #pragma unroll
    for (int i = 0; i < 4; i++) {
        const int r0 = m0 + wm + i * 16 + (lane >> 2);
        const int r1 = r0 + 8;
        #pragma unroll
        for (int j = 0; j < 4; j++) {
            const int c = n0 + wn + j * 8 + (lane & 3) * 2;
            if (r0 < M) {
                if (c < N)     g_S[(size_t)r0 * N + c]     = acc[i][j][0];
                if (c + 1 < N) g_S[(size_t)r0 * N + c + 1] = acc[i][j][1];
            }
            if (r1 < M) {
                if (c < N)     g_S[(size_t)r1 * N + c]     = acc[i][j][2];
                if (c + 1 < N) g_S[(size_t)r1 * N + c + 1] = acc[i][j][3];
            }
        }
    }
}

// ---------------- transpose weights: W[K][1024] -> Wt[1024][K] --------------------
__global__ void __launch_bounds__(256) transW(
    const float* __restrict__ W, float* __restrict__ Wt, int K)
{
    __shared__ float t[32][33];
    const int n0 = blockIdx.x * 32, k0 = blockIdx.y * 32;
    const int tx = threadIdx.x & 31, ty = threadIdx.x >> 5;
    #pragma unroll
    for (int j = 0; j < 4; j++)
        t[ty + j * 8][tx] = W[(size_t)(k0 + ty + j * 8) * DDIM + n0 + tx];
    __syncthreads();
    #pragma unroll
    for (int j = 0; j < 4; j++) {
        const int row = ty + j * 8;
        Wt[(size_t)(n0 + row) * K + k0 + tx] = t[tx][row];
    }
}

// ---------------- setup: masks, scans, compacted index lists ---------------------
__global__ void __launch_bounds__(1024) setup_kernel(const int* __restrict__ missing) {
    __shared__ int sh[1024];
    const int t = threadIdx.x;
    const int base = t * 8;
    for (int m = 0; m < 3; m++) {
        const int tag = m + 1;
        int a[8];
        int cnt = 0;
        #pragma unroll
        for (int j = 0; j < 8; j++) { a[j] = (missing[base + j] != tag) ? 1 : 0; cnt += a[j]; }
        sh[t] = cnt; __syncthreads();
        for (int off = 1; off < 1024; off <<= 1) {
            int v = (t >= off) ? sh[t - off] : 0; __syncthreads();
            sh[t] += v; __syncthreads();
        }
        const int Nb = sh[1023];
        int pos = sh[t] - cnt;
        #pragma unroll
        for (int j = 0; j < 8; j++) if (a[j]) g_glist[m][pos++] = base + j;
        if (t == 0) g_cnt[m][0] = Nb;
        __syncthreads();
        int qf[8]; cnt = 0;
        #pragma unroll
        for (int j = 0; j < 8; j++) {
            qf[j] = ((missing[base + j] == tag) && (base + j < Nb)) ? 1 : 0; cnt += qf[j];
        }
        sh[t] = cnt; __syncthreads();
        for (int off = 1; off < 1024; off <<= 1) {
            int v = (t >= off) ? sh[t - off] : 0; __syncthreads();
            sh[t] += v; __syncthreads();
        }
        const int nq = sh[1023];
        pos = sh[t] - cnt;
        #pragma unroll
        for (int j = 0; j < 8; j++) if (qf[j]) {
            g_qidx[m][pos] = base + j;
            g_qrow[m][pos] = g_glist[m][base + j];
            pos++;
        }
        if (t == 0) g_cnt[m][1] = nq;
        __syncthreads();
        int cf[8]; cnt = 0;
        #pragma unroll
        for (int j = 0; j < 8; j++) { cf[j] = (a[j] && (base + j < Nb)) ? 1 : 0; cnt += cf[j]; }
        sh[t] = cnt; __syncthreads();
        for (int off = 1; off < 1024; off <<= 1) {
            int v = (t >= off) ? sh[t - off] : 0; __syncthreads();
            sh[t] += v; __syncthreads();
        }
        const int nc = sh[1023];
        pos = sh[t] - cnt;
        #pragma unroll
        for (int j = 0; j < 8; j++) if (cf[j]) {
            g_cidx[m][pos] = base + j;
            g_crow[m][pos] = g_glist[m][base + j];
            pos++;
        }
        if (t == 0) g_cnt[m][2] = nc;
        __syncthreads();
    }
}

// ---------------- per-bank-row L2 norms --------------------------------------------
__global__ void __launch_bounds__(256) knorm(int m) {
    const int i = blockIdx.x;
    if (i >= g_cnt[m][0]) return;
    const int row = g_glist[m][i];
    const float4* p = reinterpret_cast<const float4*>(
        g_proj + (size_t)m * BSZ * DDIM + (size_t)row * DDIM);
    float4 v = p[threadIdx.x];
    float s = v.x * v.x + v.y * v.y + v.z * v.z + v.w * v.w;
    #pragma unroll
    for (int off = 16; off > 0; off >>= 1) s += __shfl_down_sync(0xffffffffu, s, off);
    __shared__ float red[8];
    if ((threadIdx.x & 31) == 0) red[threadIdx.x >> 5] = s;
    __syncthreads();
    if (threadIdx.x == 0) {
        float tot = 0.f;
        #pragma unroll
        for (int w = 0; w < 8; w++) tot += red[w];
        g_nrm[i] = fmaxf(__fsqrt_rn(tot), 1e-8f);
    }
}

// ---------------- gather normalized query / candidate matrices ---------------------
__global__ void __launch_bounds__(256) kgather(int m) {
    const int i = blockIdx.x, t = threadIdx.x;
    const float* __restrict__ projm = g_proj + (size_t)m * BSZ * DDIM;
    if (i < g_cnt[m][1]) {
        const float nr = g_nrm[g_qidx[m][i]];
        float4 v = reinterpret_cast<const float4*>(projm + (size_t)g_qrow[m][i] * DDIM)[t];
        float4 o = make_float4(__fdiv_rn(v.x, nr), __fdiv_rn(v.y, nr),
                               __fdiv_rn(v.z, nr), __fdiv_rn(v.w, nr));
        reinterpret_cast<float4*>(g_Qn + (size_t)i * DDIM)[t] = o;
    }
    if (i < g_cnt[m][2]) {
        const float nr = g_nrm[g_cidx[m][i]];
        float4 v = reinterpret_cast<const float4*>(projm + (size_t)g_crow[m][i] * DDIM)[t];
        float4 o = make_float4(__fdiv_rn(v.x, nr), __fdiv_rn(v.y, nr),
                               __fdiv_rn(v.z, nr), __fdiv_rn(v.w, nr));
        reinterpret_cast<float4*>(g_Cn + (size_t)i * DDIM)[t] = o;
    }
}

// ---------------- zero rows: missing && b >= Nb -------------------------------------
__global__ void __launch_bounds__(256) kzero(const int* __restrict__ missing, int m) {
    const int b = blockIdx.x;
    if (missing[b] != m + 1) return;
    if (b < g_cnt[m][0]) return;
    reinterpret_cast<float4*>(g_proj + (size_t)m * BSZ * DDIM + (size_t)b * DDIM)[threadIdx.x] =
        make_float4(0.f, 0.f, 0.f, 0.f);
}

// ---------------- top-3 + softmax + weighted gather, in-place fill ------------------
__global__ void __launch_bounds__(256) ktopk(int m) {
    const int q = blockIdx.x;
    const int nq = g_cnt[m][1];
    if (q >= nq) return;
    const int nc = g_cnt[m][2];
    const int t = threadIdx.x;
    float* __restrict__ projm = g_proj + (size_t)m * BSZ * DDIM;
    float* __restrict__ dst = projm + (size_t)g_qidx[m][q] * DDIM;
    if (nc == 0) {
        reinterpret_cast<float4*>(dst)[t] = make_float4(0.f, 0.f, 0.f, 0.f);
        return;
    }
    const float NEGINF = -INFINITY;
    const float* __restrict__ Srow = g_S + (size_t)q * nc;
    float v0 = NEGINF, v1 = NEGINF, v2 = NEGINF;
    int   i0 = 0x7fffffff, i1 = 0x7fffffff, i2 = 0x7fffffff;
    for (int c = t; c < nc; c += 256) {
        float v = Srow[c];
        if (v > v2) {
            if (v > v1) {
                if (v > v0) { v2 = v1; i2 = i1; v1 = v0; i1 = i0; v0 = v; i0 = c; }
                else        { v2 = v1; i2 = i1; v1 = v;  i1 = c; }
            } else          { v2 = v;  i2 = c; }
        }
    }
    __shared__ float sv[768];
    __shared__ int   si[768];
    sv[t] = v0; sv[256 + t] = v1; sv[512 + t] = v2;
    si[t] = i0; si[256 + t] = i1; si[512 + t] = i2;
    __syncthreads();
    __shared__ float fw[3];
    __shared__ int   fr[3];
    if (t == 0) {
        float b0 = NEGINF, b1 = NEGINF, b2 = NEGINF;
        int   j0 = 0x7fffffff, j1 = 0x7fffffff, j2 = 0x7fffffff;
        for (int e = 0; e < 768; e++) {
            float v = sv[e]; int c = si[e];
            if ((v > b2) || (v == b2 && c < j2)) {
                if ((v > b1) || (v == b1 && c < j1)) {
                    if ((v > b0) || (v == b0 && c < j0)) {
                        b2 = b1; j2 = j1; b1 = b0; j1 = j0; b0 = v; j0 = c;
                    } else { b2 = b1; j2 = j1; b1 = v; j1 = c; }
                } else     { b2 = v; j2 = c; }
            }
        }
        float w0 = 1.0f;
        float w1 = (b1 == NEGINF) ? 0.f : expf(b1 - b0);
        float w2 = (b2 == NEGINF) ? 0.f : expf(b2 - b0);
        float ws = w0 + w1 + w2;
        fw[0] = __fdiv_rn(w0, ws); fw[1] = __fdiv_rn(w1, ws); fw[2] = __fdiv_rn(w2, ws);
        fr[0] = (j0 == 0x7fffffff) ? 0 : g_crow[m][j0];
        fr[1] = (j1 == 0x7fffffff) ? 0 : g_crow[m][j1];
        fr[2] = (j2 == 0x7fffffff) ? 0 : g_crow[m][j2];
    }
    __syncthreads();
    const float w0 = fw[0], w1 = fw[1], w2 = fw[2];
    float4 a = reinterpret_cast<const float4*>(projm + (size_t)fr[0] * DDIM)[t];
    float4 b = reinterpret_cast<const float4*>(projm + (size_t)fr[1] * DDIM)[t];
    float4 c = reinterpret_cast<const float4*>(projm + (size_t)fr[2] * DDIM)[t];
    float4 o;
    o.x = w0 * a.x + w1 * b.x + w2 * c.x;
    o.y = w0 * a.y + w1 * b.y + w2 * c.y;
    o.z = w0 * a.z + w1 * b.z + w2 * c.z;
    o.w = w0 * a.w + w1 * b.w + w2 * c.w;
    reinterpret_cast<float4*>(dst)[t] = o;
}

// ---------------- MLP layer 2: out = h @ W2 + b2 -----------------------------------
__global__ void __launch_bounds__(256) kmlp2(
    const float* __restrict__ W2, const float* __restrict__ b2, float* __restrict__ out)
{
    const int b = blockIdx.x, t = threadIdx.x;
    float4 h = reinterpret_cast<const float4*>(g_h + (size_t)b * DDIM)[t];
    float4 w = reinterpret_cast<const float4*>(W2)[t];
    float s = h.x * w.x + h.y * w.y + h.z * w.z + h.w * w.w;
    #pragma unroll
    for (int off = 16; off > 0; off >>= 1) s += __shfl_down_sync(0xffffffffu, s, off);
    __shared__ float red[8];
    if ((t & 31) == 0) red[t >> 5] = s;
    __syncthreads();
    if (t == 0) {
        float tot = 0.f;
        #pragma unroll
        for (int wq = 0; wq < 8; wq++) tot += red[wq];
        out[b] = tot + b2[0];
    }
}

// ---------------- launch -------------------------------------------------------------
extern "C" void kernel_launch(void* const* d_in, const int* in_sizes, int n_in,
                              void* d_out, int out_size) {
    const float* x[3]  = { (const float*)d_in[0], (const float*)d_in[1], (const float*)d_in[2] };
    const int* missing = (const int*)d_in[3];
    const float* W[3]  = { (const float*)d_in[4], (const float*)d_in[6], (const float*)d_in[8] };
    const float* bb[3] = { (const float*)d_in[5], (const float*)d_in[7], (const float*)d_in[9] };
    const float* W1 = (const float*)d_in[10];
    const float* b1 = (const float*)d_in[11];
    const float* W2 = (const float*)d_in[12];
    const float* b2 = (const float*)d_in[13];
    float* out = (float*)d_out;

    setup_kernel<<<1, 1024>>>(missing);

    float* wtd = nullptr;
    cudaGetSymbolAddress((void**)&wtd, g_Wt);
    float* w1td = nullptr;
    cudaGetSymbolAddress((void**)&w1td, g_W1t);
    for (int m = 0; m < 3; m++)
        transW<<<dim3(32, FDIM / 32), 256>>>(W[m], wtd + (size_t)m * DDIM * FDIM, FDIM);
    transW<<<dim3(32, HDIM / 32), 256>>>(W1, w1td, HDIM);

    dim3 gp(DDIM / 128, BSZ / 128);                 // (8, 64)
    for (int m = 0; m < 3; m++)
        tgemm_bias<<<gp, 256>>>(m, x[m], bb[m]);

    dim3 gs(64, 64);                                // early-exit on runtime dims
    for (int m = 0; m < 3; m++) {
        knorm<<<BSZ, 256>>>(m);
        kgather<<<BSZ, 256>>>(m);
        kzero<<<BSZ, 256>>>(missing, m);
        tgemm_sim<<<gs, 256>>>(m);
        ktopk<<<BSZ, 256>>>(m);
    }

    tgemm_bias<<<gp, 256>>>(3, nullptr, b1);
    kmlp2<<<BSZ, 256>>>(W2, b2, out);
}